// round 15
// baseline (speedup 1.0000x reference)
#include <cuda_runtime.h>
#include <cuda_fp16.h>
#include <math.h>
#include <stdint.h>

#define BATCH 8
#define SEQ   2048
#define DIM   1024
#define BS    (BATCH * SEQ)   // 16384
#define HB    (BATCH / 2)     // 4 batches per half
#define HROWS (HB * SEQ)      // 8192 rows per half

// ---------------------------------------------------------------------------
// Scratch (__device__ globals: allocation-free rule)
// ---------------------------------------------------------------------------
__device__ __half g_xb_hi[BS * DIM], g_xb_lo[BS * DIM];
__device__ __half g_wT_hi[3 * DIM * DIM], g_wT_lo[3 * DIM * DIM];   // WqT,WkT,WvT [h][e]
__device__ __half g_lwT_hi[DIM * DIM], g_lwT_lo[DIM * DIM];          // lwT [d][e]
__device__ __half g_c_hi[3 * DIM * DIM], g_c_lo[3 * DIM * DIM];      // combined W' [h][d]
__device__ float  g_bias[3 * DIM];                                   // bq,bk,bv
__device__ __half g_qkv_hi[2LL * BS * DIM], g_qkv_lo[2LL * BS * DIM];// Q,K splits
__device__ __half g_v_hi[(long long)BS * DIM];                       // V hi split [k][h]
__device__ __half g_p_hi [(long long)BATCH * SEQ * SEQ], g_p_lo [(long long)BATCH * SEQ * SEQ];
__device__ float  g_s[(long long)BATCH * SEQ * SEQ];

// ---------------------------------------------------------------------------
// helpers
// ---------------------------------------------------------------------------
__device__ __forceinline__ uint32_t smem_u32(const void* p) {
    uint32_t a;
    asm("{ .reg .u64 t; cvta.to.shared.u64 t, %1; cvt.u32.u64 %0, t; }"
        : "=r"(a) : "l"(p));
    return a;
}

__device__ __forceinline__ void cp16(uint32_t saddr, const void* gaddr) {
    asm volatile("cp.async.cg.shared.global [%0], [%1], 16;" :: "r"(saddr), "l"(gaddr));
}
__device__ __forceinline__ void cp_commit() {
    asm volatile("cp.async.commit_group;" ::: "memory");
}
template<int N>
__device__ __forceinline__ void cp_wait_c() {
    asm volatile("cp.async.wait_group %0;" :: "n"(N) : "memory");
}

__device__ __forceinline__ void ldsm4(uint32_t (&r)[4], uint32_t addr) {
    asm volatile("ldmatrix.sync.aligned.m8n8.x4.shared.b16 {%0,%1,%2,%3}, [%4];"
        : "=r"(r[0]), "=r"(r[1]), "=r"(r[2]), "=r"(r[3]) : "r"(addr));
}
__device__ __forceinline__ void ldsm4t(uint32_t (&r)[4], uint32_t addr) {
    asm volatile("ldmatrix.sync.aligned.m8n8.x4.trans.shared.b16 {%0,%1,%2,%3}, [%4];"
        : "=r"(r[0]), "=r"(r[1]), "=r"(r[2]), "=r"(r[3]) : "r"(addr));
}

__device__ __forceinline__ void mma_f16(float* c, const uint32_t* a, const uint32_t* b) {
    asm volatile("mma.sync.aligned.m16n8k16.row.col.f32.f16.f16.f32 "
        "{%0,%1,%2,%3}, {%4,%5,%6,%7}, {%8,%9}, {%0,%1,%2,%3};"
        : "+f"(c[0]), "+f"(c[1]), "+f"(c[2]), "+f"(c[3])
        : "r"(a[0]), "r"(a[1]), "r"(a[2]), "r"(a[3]), "r"(b[0]), "r"(b[1]));
}

// SW64 swizzle for 64B rows — conflict-free ldmatrix
__device__ __forceinline__ uint32_t sw64(uint32_t off) {
    return off ^ ((off >> 3) & 0x30);
}
// SW256 swizzle for 256B rows (NN B tiles)
__device__ __forceinline__ uint32_t sw256(uint32_t off) {
    return off ^ ((off >> 4) & 0x70);
}

__device__ __forceinline__ void split1(float v, __half& h, __half& l) {
    h = __float2half(v);
    l = __float2half(v - __half2float(h));
}

// ---------------------------------------------------------------------------
// split-fp16 GEMM on HMMA — 4 warps, 64x64 warp tiles, 3 CTAs/SM.
//  BNN=false: C[M,N] = (Ahi+Alo)[M,K] * (Bhi+Blo)[N,K]^T  (NT)
//  BNN=true : C[M,N] = (Ahi+Alo)[M,K] * (Bhi)[K,N]        (NN, ldmatrix.trans)
// TERMS=3: Ah*Bh + Al*Bh + Ah*Bl ;  TERMS=2: Ah*Bh + Al*Bh
// 128x128 CTA tile, BK=32, 2-stage cp.async (cross-CTA latency hiding),
// 128 threads, 3 CTAs/SM (65KB smem, <=170 regs).
// EPI: 0=f32, 1=hi+lo, 2=f32+hi+lo, 3=f32+hi only
// SKIPZ0: suppress fp32 store for z==0
// ---------------------------------------------------------------------------
#define NSTG 2
#define TILE_BYTES  8192
#define STAGE_BYTES (4 * TILE_BYTES)
#define SMEM_DYN    (NSTG * STAGE_BYTES + 1024)   // 66560

// load one 128x32 fp16 tile, SW64-swizzled (4 cp16 per thread @128 thr)
__device__ __forceinline__ void load_tile(const __half* __restrict__ g,
                                          int row0, int k0, int ld,
                                          uint32_t sdst, int tid) {
    #pragma unroll
    for (int i = 0; i < 4; i++) {
        int gr = i * 128 + tid;          // 0..511
        int r  = gr >> 2;
        int sec = gr & 3;
        cp16(sdst + sw64((uint32_t)(r * 64 + sec * 16)),
             (const void*)(g + (long long)(row0 + r) * ld + (k0 + sec * 8)));
    }
}

// NN: load one 32(k) x 128(n) fp16 tile (256B rows), SW256-swizzled
__device__ __forceinline__ void load_tile_nn(const __half* __restrict__ g,
                                             int k0, int col0, int ld,
                                             uint32_t sdst, int tid) {
    #pragma unroll
    for (int i = 0; i < 4; i++) {
        int gr = i * 128 + tid;          // 0..511
        int r  = gr >> 4;
        int sec = gr & 15;
        cp16(sdst + sw256((uint32_t)(r * 256 + sec * 16)),
             (const void*)(g + (long long)(k0 + r) * ld + (col0 + sec * 8)));
    }
}

template<int EPI, bool BIAS, bool CAUSAL, bool KLIM, int TERMS, bool SKIPZ0, bool BNN>
__global__ void __launch_bounds__(128, 3)
gemm_mma(const __half* __restrict__ Ahi, const __half* __restrict__ Alo,
         const __half* __restrict__ Bhi, const __half* __restrict__ Blo,
         const float* __restrict__ bias,
         float* __restrict__ Cf, __half* __restrict__ Chi, __half* __restrict__ Clo,
         int K, int ldC,
         long long aB, long long bB, long long cB)
{
    const int bx = blockIdx.x, z = blockIdx.z;
    int by = blockIdx.y;
    if (CAUSAL && bx > by) return;
    if (KLIM) by = gridDim.y - 1 - by;    // longest tiles first

    extern __shared__ char smem[];
    const uint32_t stage0 = (smem_u32(smem) + 1023u) & ~1023u;

    const int tid  = threadIdx.x;
    const int lane = tid & 31;
    const int wid  = tid >> 5;            // 0..3
    const int wm   = (wid & 1) * 64;      // warp m offset
    const int wn   = (wid >> 1) * 64;     // warp n offset

    const __half* A_hi = Ahi + (long long)z * aB;
    const __half* A_lo = Alo + (long long)z * aB;
    const __half* B_hi = Bhi + (long long)z * bB;
    const __half* B_lo = Blo + (long long)z * bB;

    int nk = K >> 5;
    if (KLIM) { int lim = 4 * (by + 1); if (lim < nk) nk = lim; }
    const int row0 = by * 128;
    const int col0 = bx * 128;

    float acc[4][8][4];
    #pragma unroll
    for (int i = 0; i < 4; i++)
        #pragma unroll
        for (int j = 0; j < 8; j++)
            #pragma unroll
            for (int c = 0; c < 4; c++) acc[i][j][c] = 0.0f;

    // per-lane ldmatrix address components
    const int a_r = ((lane >> 3) & 1) * 8 + (lane & 7);   // + mi*16 + wm
    const int a_c = (lane >> 4) * 16;                      // + ks*32
    const int b_r = ((lane >> 4) & 1) * 8 + (lane & 7);    // + pair*16 + wn
    const int b_c = ((lane >> 3) & 1) * 16;                // + ks*32
    const int bt_r = ((lane >> 3) & 1) * 8 + (lane & 7);   // NN: k row in 16-block
    const int bt_c = ((lane >> 4) & 1) * 16;               // NN: n byte in 32B pair

    // prologue: 1 chunk in flight
    {
        uint32_t st = stage0;
        load_tile(A_hi, row0, 0, K, st + 0 * TILE_BYTES, tid);
        load_tile(A_lo, row0, 0, K, st + 1 * TILE_BYTES, tid);
        if (BNN)
            load_tile_nn(B_hi, 0, col0, ldC, st + 2 * TILE_BYTES, tid);
        else
            load_tile(B_hi, col0, 0, K, st + 2 * TILE_BYTES, tid);
        if (!BNN && TERMS >= 3)
            load_tile(B_lo, col0, 0, K, st + 3 * TILE_BYTES, tid);
        cp_commit();
    }

    for (int k = 0; k < nk; k++) {
        const int s = k & 1;
        cp_wait_c<0>();
        __syncthreads();

        const uint32_t sAh = stage0 + s * STAGE_BYTES + 0 * TILE_BYTES;
        const uint32_t sAl = sAh + TILE_BYTES;
        const uint32_t sBh = sAh + 2 * TILE_BYTES;
        const uint32_t sBl = sAh + 3 * TILE_BYTES;

        #pragma unroll
        for (int ks = 0; ks < 2; ks++) {
            uint32_t ah[4][4], bh[4][4];
            #pragma unroll
            for (int mi = 0; mi < 4; mi++)
                ldsm4(ah[mi], sAh + sw64((uint32_t)((wm + mi * 16 + a_r) * 64 + ks * 32 + a_c)));
            #pragma unroll
            for (int p = 0; p < 4; p++) {
                if (BNN)
                    ldsm4t(bh[p], sBh + sw256((uint32_t)((ks * 16 + bt_r) * 256 + wn * 2 + p * 32 + bt_c)));
                else
                    ldsm4(bh[p], sBh + sw64((uint32_t)((wn + p * 16 + b_r) * 64 + ks * 32 + b_c)));
            }
            // term 1: Ah*Bh
            #pragma unroll
            for (int mi = 0; mi < 4; mi++)
                #pragma unroll
                for (int nj = 0; nj < 8; nj++)
                    mma_f16(acc[mi][nj], ah[mi], &bh[nj >> 1][(nj & 1) * 2]);
            // term 2: Al*Bh
            {
                uint32_t al[4][4];
                #pragma unroll
                for (int mi = 0; mi < 4; mi++)
                    ldsm4(al[mi], sAl + sw64((uint32_t)((wm + mi * 16 + a_r) * 64 + ks * 32 + a_c)));
                #pragma unroll
                for (int mi = 0; mi < 4; mi++)
                    #pragma unroll
                    for (int nj = 0; nj < 8; nj++)
                        mma_f16(acc[mi][nj], al[mi], &bh[nj >> 1][(nj & 1) * 2]);
            }
            // term 3: Ah*Bl (NT only)
            if (!BNN && TERMS >= 3) {
                uint32_t bl[4][4];
                #pragma unroll
                for (int p = 0; p < 4; p++)
                    ldsm4(bl[p], sBl + sw64((uint32_t)((wn + p * 16 + b_r) * 64 + ks * 32 + b_c)));
                #pragma unroll
                for (int mi = 0; mi < 4; mi++)
                    #pragma unroll
                    for (int nj = 0; nj < 8; nj++)
                        mma_f16(acc[mi][nj], ah[mi], &bl[nj >> 1][(nj & 1) * 2]);
            }
        }

        // prefetch chunk k+1 (tail placement — measured best)
        const int cl = k + 1;
        if (cl < nk) {
            uint32_t st = stage0 + (cl & 1) * STAGE_BYTES;
            load_tile(A_hi, row0, cl * 32, K, st + 0 * TILE_BYTES, tid);
            load_tile(A_lo, row0, cl * 32, K, st + 1 * TILE_BYTES, tid);
            if (BNN)
                load_tile_nn(B_hi, cl * 32, col0, ldC, st + 2 * TILE_BYTES, tid);
            else
                load_tile(B_hi, col0, cl * 32, K, st + 2 * TILE_BYTES, tid);
            if (!BNN && TERMS >= 3)
                load_tile(B_lo, col0, cl * 32, K, st + 3 * TILE_BYTES, tid);
            cp_commit();
        }
    }

    // ---- epilogue (64x64 per warp) ----
    const float* bp = bias + (long long)z * DIM;
    const bool doF32 = (EPI == 0 || EPI >= 2) && !(SKIPZ0 && z == 0);
    #pragma unroll
    for (int mi = 0; mi < 4; mi++) {
        const int r0 = row0 + wm + mi * 16 + (lane >> 2);
        #pragma unroll
        for (int nj = 0; nj < 8; nj++) {
            const int c = col0 + wn + nj * 8 + (lane & 3) * 2;
            float v0 = acc[mi][nj][0], v1 = acc[mi][nj][1];
            float v2 = acc[mi][nj][2], v3 = acc[mi][nj][3];
            if (BIAS) {
                float b0 = bp[c], b1 = bp[c + 1];
                v0 += b0; v1 += b1; v2 += b0; v3 += b1;
            }
            if (doF32) {
                float* cp = Cf + (long long)z * cB + (long long)r0 * ldC + c;
                *(float2*)cp = make_float2(v0, v1);
                *(float2*)(cp + 8LL * ldC) = make_float2(v2, v3);
            }
            if (EPI == 1 || EPI == 2 || EPI == 3) {
                __half h0, l0, h1, l1;
                split1(v0, h0, l0); split1(v1, h1, l1);
                __half* hp = Chi + (long long)z * cB + (long long)r0 * ldC + c;
                *(__half2*)hp = __halves2half2(h0, h1);
                if (EPI != 3) {
                    __half* lp = Clo + (long long)z * cB + (long long)r0 * ldC + c;
                    *(__half2*)lp = __halves2half2(l0, l1);
                    split1(v2, h0, l0); split1(v3, h1, l1);
                    *(__half2*)(hp + 8LL * ldC) = __halves2half2(h0, h1);
                    *(__half2*)(lp + 8LL * ldC) = __halves2half2(l0, l1);
                } else {
                    split1(v2, h0, l0); split1(v3, h1, l1);
                    *(__half2*)(hp + 8LL * ldC) = __halves2half2(h0, h1);
                }
            }
        }
    }
}

// ---------------------------------------------------------------------------
// elementwise fp32 -> fp16 hi/lo split
// ---------------------------------------------------------------------------
__global__ void split_kernel(const float* __restrict__ in,
                             __half* __restrict__ hi,
                             __half* __restrict__ lo, int n4)
{
    int i = blockIdx.x * blockDim.x + threadIdx.x;
    if (i >= n4) return;
    float4 v = ((const float4*)in)[i];
    __half h0, l0, h1, l1, h2, l2, h3, l3;
    split1(v.x, h0, l0); split1(v.y, h1, l1);
    split1(v.z, h2, l2); split1(v.w, h3, l3);
    __half2 ha = __halves2half2(h0, h1), hb = __halves2half2(h2, h3);
    __half2 la = __halves2half2(l0, l1), lb = __halves2half2(l2, l3);
    ((uint2*)hi)[i] = make_uint2(*(uint32_t*)&ha, *(uint32_t*)&hb);
    ((uint2*)lo)[i] = make_uint2(*(uint32_t*)&la, *(uint32_t*)&lb);
}

// transpose + split: fp32 [Z][R][C] -> fp16 hi/lo [Z][C][R]  (weights only)
__global__ void tsplit_kernel(const float* __restrict__ in,
                              __half* __restrict__ hi,
                              __half* __restrict__ lo, int R, int C)
{
    __shared__ float t[32][33];
    const long long zoff = (long long)blockIdx.z * R * C;
    const int c0 = blockIdx.x * 32, r0 = blockIdx.y * 32;
    const int tx = threadIdx.x, ty = threadIdx.y;
    #pragma unroll
    for (int i = 0; i < 4; i++)
        t[ty + 8 * i][tx] = in[zoff + (long long)(r0 + ty + 8 * i) * C + c0 + tx];
    __syncthreads();
    #pragma unroll
    for (int i = 0; i < 4; i++) {
        float v = t[tx][ty + 8 * i];
        __half h, l; split1(v, h, l);
        long long o = zoff + (long long)(c0 + ty + 8 * i) * R + r0 + tx;
        hi[o] = h; lo[o] = l;
    }
}

// ---------------------------------------------------------------------------
// combined biases: out[j*DIM + h] = sum_e b[e] * W_j[e, h],  j in {q,k,v}
// ---------------------------------------------------------------------------
__global__ void bias_combine_kernel(const float* __restrict__ b,
                                    const float* __restrict__ Wq,
                                    const float* __restrict__ Wk,
                                    const float* __restrict__ Wv,
                                    float* __restrict__ out)
{
    const int h = blockIdx.x * 256 + threadIdx.x;
    const float* W = (blockIdx.y == 0) ? Wq : (blockIdx.y == 1) ? Wk : Wv;
    float s = 0.0f;
    #pragma unroll 8
    for (int e = 0; e < DIM; e++) s += b[e] * W[(long long)e * DIM + h];
    out[blockIdx.y * DIM + h] = s;
}

// ---------------------------------------------------------------------------
// causal softmax fp32 scores -> fp16 hi/lo probs (vectorized)
// ---------------------------------------------------------------------------
__global__ __launch_bounds__(256)
void softmax_causal_kernel(const float* __restrict__ S,
                           __half* __restrict__ Phi,
                           __half* __restrict__ Plo)
{
    const int q = blockIdx.x, b = blockIdx.y;
    const long long off = ((long long)b * SEQ + q) * SEQ;
    const float* row = S + off;
    const int n = q + 1;
    const int n4 = n >> 2;
    const int rem = n & 3;
    const int tid = threadIdx.x;
    __shared__ float sh[8];

    float4 rv[2];
    float tail = 0.0f;
    int cnt = 0;
    float m = -INFINITY;
    for (int i = tid; i < n4; i += 256) {
        float4 v = ((const float4*)row)[i];
        rv[cnt++] = v;
        m = fmaxf(fmaxf(m, fmaxf(v.x, v.y)), fmaxf(v.z, v.w));
    }
    const bool hasTail = (tid < rem);
    if (hasTail) {
        tail = row[n4 * 4 + tid];
        m = fmaxf(m, tail);
    }
    #pragma unroll
    for (int o = 16; o; o >>= 1) m = fmaxf(m, __shfl_xor_sync(0xffffffffu, m, o));
    if ((tid & 31) == 0) sh[tid >> 5] = m;
    __syncthreads();
    float mr = sh[0];
    #pragma unroll
    for (int i = 1; i < 8; i++) mr = fmaxf(mr, sh[i]);
    __syncthreads();

    float s = 0.0f;
    #pragma unroll
    for (int j = 0; j < 2; j++)
        if (j < cnt) {
            rv[j].x = __expf(rv[j].x - mr); rv[j].y = __expf(rv[j].y - mr);
            rv[j].z = __expf(rv[j].z - mr); rv[j].w = __expf(rv[j].w - mr);
            s += rv[j].x + rv[j].y + rv[j].z + rv[j].w;
        }
    if (hasTail) { tail = __expf(tail - mr); s += tail; }
    #pragma unroll
    for (int o = 16; o; o >>= 1) s += __shfl_xor_sync(0xffffffffu, s, o);
    if ((tid & 31) == 0) sh[tid >> 5] = s;
    __syncthreads();
    float sr = 0.0f;
    #pragma unroll
    for (int i = 0; i < 8; i++) sr += sh[i];
    const float inv = 1.0f / sr;

    cnt = 0;
    for (int i = tid; i < n4; i += 256) {
        float4 v = rv[cnt++];
        float p0 = v.x * inv, p1 = v.y * inv, p2 = v.z * inv, p3 = v.w * inv;
        __half h0, l0, h1, l1, h2, l2, h3, l3;
        split1(p0, h0, l0); split1(p1, h1, l1);
        split1(p2, h2, l2); split1(p3, h3, l3);
        __half2 ha = __halves2half2(h0, h1), hb = __halves2half2(h2, h3);
        __half2 la = __halves2half2(l0, l1), lb = __halves2half2(l2, l3);
        ((uint2*)(Phi + off))[i] = make_uint2(*(uint32_t*)&ha, *(uint32_t*)&hb);
        ((uint2*)(Plo + off))[i] = make_uint2(*(uint32_t*)&la, *(uint32_t*)&lb);
    }
    if (hasTail) {
        float p = tail * inv;
        __half h, l; split1(p, h, l);
        Phi[off + n4 * 4 + tid] = h; Plo[off + n4 * 4 + tid] = l;
    }
    const int fend = ((q >> 7) + 1) << 7;
    const __half z16 = __float2half(0.0f);
    for (int i = n + tid; i < fend; i += 256) {
        Phi[off + i] = z16; Plo[off + i] = z16;
    }
}

// ---------------------------------------------------------------------------
extern "C" void kernel_launch(void* const* d_in, const int* in_sizes, int n_in,
                              void* d_out, int out_size)
{
    const float* x_batch = (const float*)d_in[0];
    const float* lin_w   = (const float*)d_in[1];
    const float* lin_b   = (const float*)d_in[2];
    const float* W_q     = (const float*)d_in[3];
    const float* W_k     = (const float*)d_in[4];
    const float* W_v     = (const float*)d_in[5];

    float* outF = (float*)d_out;
    float* outK = outF + (long long)BS * DIM;
    float* outV = outK + (long long)BS * DIM;

    __half *xb_hi, *xb_lo, *wT_hi, *wT_lo, *lwT_hi, *lwT_lo, *c_hi, *c_lo;
    __half *qkv_hi, *qkv_lo, *v_hi, *p_hi, *p_lo;
    float *bias3, *ss;
    cudaGetSymbolAddress((void**)&xb_hi, g_xb_hi); cudaGetSymbolAddress((void**)&xb_lo, g_xb_lo);
    cudaGetSymbolAddress((void**)&wT_hi, g_wT_hi); cudaGetSymbolAddress((void**)&wT_lo, g_wT_lo);
    cudaGetSymbolAddress((void**)&lwT_hi, g_lwT_hi); cudaGetSymbolAddress((void**)&lwT_lo, g_lwT_lo);
    cudaGetSymbolAddress((void**)&c_hi, g_c_hi);   cudaGetSymbolAddress((void**)&c_lo, g_c_lo);
    cudaGetSymbolAddress((void**)&bias3, g_bias);
    cudaGetSymbolAddress((void**)&qkv_hi, g_qkv_hi); cudaGetSymbolAddress((void**)&qkv_lo, g_qkv_lo);
    cudaGetSymbolAddress((void**)&v_hi, g_v_hi);
    cudaGetSymbolAddress((void**)&p_hi,  g_p_hi);  cudaGetSymbolAddress((void**)&p_lo,  g_p_lo);
    cudaGetSymbolAddress((void**)&ss, g_s);

    cudaFuncSetAttribute(gemm_mma<1, false, false, false, 3, false, false>, cudaFuncAttributeMaxDynamicSharedMemorySize, SMEM_DYN);
    cudaFuncSetAttribute(gemm_mma<2, true,  false, false, 3, true,  false>, cudaFuncAttributeMaxDynamicSharedMemorySize, SMEM_DYN);
    cudaFuncSetAttribute(gemm_mma<3, true,  false, false, 3, false, false>, cudaFuncAttributeMaxDynamicSharedMemorySize, SMEM_DYN);
    cudaFuncSetAttribute(gemm_mma<0, false, true,  false, 3, false, false>, cudaFuncAttributeMaxDynamicSharedMemorySize, SMEM_DYN);
    cudaFuncSetAttribute(gemm_mma<0, false, false, true,  2, false, true >, cudaFuncAttributeMaxDynamicSharedMemorySize, SMEM_DYN);

    const long long DD   = (long long)DIM * DIM;
    const long long HOFF = (long long)HROWS * DIM;
    const long long SOFF = (long long)HB * SEQ * SEQ;
    const long long VOFF = (long long)HB * SEQ * DIM;

    static cudaStream_t s2 = nullptr;
    static cudaEvent_t e0 = nullptr, e2 = nullptr, e3 = nullptr, eV = nullptr, eE = nullptr;
    static bool tried = false;
    if (!tried) {
        tried = true;
        if (cudaStreamCreateWithFlags(&s2, cudaStreamNonBlocking) != cudaSuccess) s2 = nullptr;
        if (s2) {
            cudaEventCreateWithFlags(&e0, cudaEventDisableTiming);
            cudaEventCreateWithFlags(&e2, cudaEventDisableTiming);
            cudaEventCreateWithFlags(&e3, cudaEventDisableTiming);
            cudaEventCreateWithFlags(&eV, cudaEventDisableTiming);
            cudaEventCreateWithFlags(&eE, cudaEventDisableTiming);
        }
    }
    const bool ok = (s2 != nullptr);
    cudaStream_t sb = ok ? s2 : (cudaStream_t)0;

    // ================= fork: prep on side, xb split on main =================
    if (ok) { cudaEventRecord(e0, 0); cudaStreamWaitEvent(sb, e0, 0); }
    {
        dim3 g(DIM / 32, DIM / 32, 1), t(32, 8);
        tsplit_kernel<<<g, t, 0, sb>>>(lin_w, lwT_hi, lwT_lo, DIM, DIM);
        tsplit_kernel<<<g, t, 0, sb>>>(W_q, wT_hi + 0 * DD, wT_lo + 0 * DD, DIM, DIM);
        tsplit_kernel<<<g, t, 0, sb>>>(W_k, wT_hi + 1 * DD, wT_lo + 1 * DD, DIM, DIM);
        tsplit_kernel<<<g, t, 0, sb>>>(W_v, wT_hi + 2 * DD, wT_lo + 2 * DD, DIM, DIM);
    }
    bias_combine_kernel<<<dim3(DIM / 256, 3), 256, 0, sb>>>(lin_b, W_q, W_k, W_v, bias3);
    {
        dim3 g(DIM / 128, DIM / 128, 3);
        gemm_mma<1, false, false, false, 3, false, false><<<g, 128, SMEM_DYN, sb>>>(
            wT_hi, wT_lo, lwT_hi, lwT_lo, nullptr,
            nullptr, c_hi, c_lo, DIM, DIM, DD, 0, DD);
    }
    if (ok) cudaEventRecord(e2, sb);

    split_kernel<<<(BS * DIM / 4 + 255) / 256, 256>>>(x_batch, xb_hi, xb_lo, BS * DIM / 4);
    if (ok) { cudaStreamWaitEvent(0, e2, 0); cudaEventRecord(e3, 0); cudaStreamWaitEvent(sb, e3, 0); }

    // ====== side pipeline (half 1, b4..7): QKV -> scores -> softmax =========
    {
        dim3 g(DIM / 128, HROWS / 128, 2);
        gemm_mma<2, true, false, false, 3, true, false><<<g, 128, SMEM_DYN, sb>>>(
            xb_hi + HOFF, xb_lo + HOFF, c_hi, c_lo, bias3,
            outF + HOFF, qkv_hi + HOFF, qkv_lo + HOFF, DIM, DIM,
            0, DD, (long long)BS * DIM);
    }
    {
        dim3 g(SEQ / 128, SEQ / 128, HB);
        gemm_mma<0, false, true, false, 3, false, false><<<g, 128, SMEM_DYN, sb>>>(
            qkv_hi + HOFF, qkv_lo + HOFF,
            qkv_hi + (long long)BS * DIM + HOFF, qkv_lo + (long long)BS * DIM + HOFF,
            nullptr, ss + SOFF, nullptr, nullptr, DIM, SEQ,
            (long long)SEQ * DIM, (long long)SEQ * DIM, (long long)SEQ * SEQ);
    }
    {
        dim3 g(SEQ, HB);
        softmax_causal_kernel<<<g, 256, 0, sb>>>(ss + SOFF, p_hi + SOFF, p_lo + SOFF);
    }

    // ====== main: V GEMM (fp32 cache + hi-only split; EPI=3) ================
    {
        dim3 g(DIM / 128, BS / 128, 1);
        gemm_mma<3, true, false, false, 3, false, false><<<g, 128, SMEM_DYN>>>(
            xb_hi, xb_lo, c_hi + 2 * DD, c_lo + 2 * DD, bias3 + 2 * DIM,
            outV, v_hi, nullptr, DIM, DIM, 0, 0, (long long)BS * DIM);
    }
    if (ok) cudaEventRecord(eV, 0);

    // ====== side: PV half 1 =================================================
    if (ok) cudaStreamWaitEvent(sb, eV, 0);
    {
        dim3 g(DIM / 128, SEQ / 128, HB);
        gemm_mma<0, false, false, true, 2, false, true><<<g, 128, SMEM_DYN, sb>>>(
            p_hi + SOFF, p_lo + SOFF, v_hi + VOFF, nullptr, nullptr,
            outF + HOFF, nullptr, nullptr, SEQ, DIM,
            (long long)SEQ * SEQ, (long long)SEQ * DIM, (long long)SEQ * DIM);
    }
    if (ok) cudaEventRecord(eE, sb);

    // ====== main pipeline (half 0, b0..3) ====================================
    {
        dim3 g(DIM / 128, HROWS / 128, 2);
        gemm_mma<2, true, false, false, 3, true, false><<<g, 128, SMEM_DYN>>>(
            xb_hi, xb_lo, c_hi, c_lo, bias3,
            outF, qkv_hi, qkv_lo, DIM, DIM,
            0, DD, (long long)BS * DIM);
    }
    {
        dim3 g(SEQ / 128, SEQ / 128, HB);
        gemm_mma<0, false, true, false, 3, false, false><<<g, 128, SMEM_DYN>>>(
            qkv_hi, qkv_lo,
            qkv_hi + (long long)BS * DIM, qkv_lo + (long long)BS * DIM,
            nullptr, ss, nullptr, nullptr, DIM, SEQ,
            (long long)SEQ * DIM, (long long)SEQ * DIM, (long long)SEQ * SEQ);
    }
    {
        dim3 g(SEQ, HB);
        softmax_causal_kernel<<<g, 256>>>(ss, p_hi, p_lo);
    }
    {
        dim3 g(DIM / 128, SEQ / 128, HB);
        gemm_mma<0, false, false, true, 2, false, true><<<g, 128, SMEM_DYN>>>(
            p_hi, p_lo, v_hi, nullptr, nullptr,
            outF, nullptr, nullptr, SEQ, DIM,
            (long long)SEQ * SEQ, (long long)SEQ * DIM, (long long)SEQ * DIM);
    }
    if (ok) cudaStreamWaitEvent(0, eE, 0);
}

// round 16
// speedup vs baseline: 1.1930x; 1.1930x over previous
#include <cuda_runtime.h>
#include <cuda_fp16.h>
#include <math.h>
#include <stdint.h>

#define BATCH 8
#define SEQ   2048
#define DIM   1024
#define BS    (BATCH * SEQ)   // 16384
#define HB    (BATCH / 2)     // 4 batches per half
#define HROWS (HB * SEQ)      // 8192 rows per half

// ---------------------------------------------------------------------------
// Scratch (__device__ globals: allocation-free rule)
// ---------------------------------------------------------------------------
__device__ __half g_xb_hi[BS * DIM], g_xb_lo[BS * DIM];
__device__ __half g_wT_hi[3 * DIM * DIM], g_wT_lo[3 * DIM * DIM];   // WqT,WkT,WvT [h][e]
__device__ __half g_lwT_hi[DIM * DIM], g_lwT_lo[DIM * DIM];          // lwT [d][e]
__device__ __half g_c_hi[3 * DIM * DIM], g_c_lo[3 * DIM * DIM];      // combined W' [h][d]
__device__ float  g_bias[3 * DIM];                                   // bq,bk,bv
__device__ __half g_qkv_hi[2LL * BS * DIM], g_qkv_lo[2LL * BS * DIM];// Q,K splits
__device__ __half g_v_hi[(long long)BS * DIM];                       // V hi split [k][h]
__device__ __half g_p_hi [(long long)BATCH * SEQ * SEQ], g_p_lo [(long long)BATCH * SEQ * SEQ];
__device__ float  g_s[(long long)BATCH * SEQ * SEQ];

// ---------------------------------------------------------------------------
// helpers
// ---------------------------------------------------------------------------
__device__ __forceinline__ uint32_t smem_u32(const void* p) {
    uint32_t a;
    asm("{ .reg .u64 t; cvta.to.shared.u64 t, %1; cvt.u32.u64 %0, t; }"
        : "=r"(a) : "l"(p));
    return a;
}

__device__ __forceinline__ void cp16(uint32_t saddr, const void* gaddr) {
    asm volatile("cp.async.cg.shared.global [%0], [%1], 16;" :: "r"(saddr), "l"(gaddr));
}
__device__ __forceinline__ void cp_commit() {
    asm volatile("cp.async.commit_group;" ::: "memory");
}
template<int N>
__device__ __forceinline__ void cp_wait_c() {
    asm volatile("cp.async.wait_group %0;" :: "n"(N) : "memory");
}

__device__ __forceinline__ void ldsm4(uint32_t (&r)[4], uint32_t addr) {
    asm volatile("ldmatrix.sync.aligned.m8n8.x4.shared.b16 {%0,%1,%2,%3}, [%4];"
        : "=r"(r[0]), "=r"(r[1]), "=r"(r[2]), "=r"(r[3]) : "r"(addr));
}
__device__ __forceinline__ void ldsm4t(uint32_t (&r)[4], uint32_t addr) {
    asm volatile("ldmatrix.sync.aligned.m8n8.x4.trans.shared.b16 {%0,%1,%2,%3}, [%4];"
        : "=r"(r[0]), "=r"(r[1]), "=r"(r[2]), "=r"(r[3]) : "r"(addr));
}

__device__ __forceinline__ void mma_f16(float* c, const uint32_t* a, const uint32_t* b) {
    asm volatile("mma.sync.aligned.m16n8k16.row.col.f32.f16.f16.f32 "
        "{%0,%1,%2,%3}, {%4,%5,%6,%7}, {%8,%9}, {%0,%1,%2,%3};"
        : "+f"(c[0]), "+f"(c[1]), "+f"(c[2]), "+f"(c[3])
        : "r"(a[0]), "r"(a[1]), "r"(a[2]), "r"(a[3]), "r"(b[0]), "r"(b[1]));
}

// SW64 swizzle for 64B rows — conflict-free ldmatrix
__device__ __forceinline__ uint32_t sw64(uint32_t off) {
    return off ^ ((off >> 3) & 0x30);
}
// SW256 swizzle for 256B rows (NN B tiles)
__device__ __forceinline__ uint32_t sw256(uint32_t off) {
    return off ^ ((off >> 4) & 0x70);
}

__device__ __forceinline__ void split1(float v, __half& h, __half& l) {
    h = __float2half(v);
    l = __float2half(v - __half2float(h));
}

// ---------------------------------------------------------------------------
// split-fp16 GEMM on HMMA — 4 warps, 64x64 warp tiles (R14 config, measured
// optimum: NSTG=3, 2 CTAs/SM, tail prefetch).
//  BNN=false: C[M,N] = (Ahi+Alo)[M,K] * (Bhi+Blo)[N,K]^T  (NT)
//  BNN=true : C[M,N] = (Ahi+Alo)[M,K] * (Bhi)[K,N]        (NN, ldmatrix.trans)
// TERMS=3: Ah*Bh + Al*Bh + Ah*Bl ;  TERMS=2: Ah*Bh + Al*Bh
// 128x128 CTA tile, BK=32, 3-stage cp.async, 128 threads, 2 CTAs/SM (96KB).
// EPI: 0=f32, 1=hi+lo, 2=f32+hi+lo, 3=f32+hi only
// SKIPZ0: suppress fp32 store for z==0
// ---------------------------------------------------------------------------
#define NSTG 3
#define TILE_BYTES  8192
#define STAGE_BYTES (4 * TILE_BYTES)
#define SMEM_DYN    (NSTG * STAGE_BYTES + 1024)   // 99328

// load one 128x32 fp16 tile, SW64-swizzled (4 cp16 per thread @128 thr)
__device__ __forceinline__ void load_tile(const __half* __restrict__ g,
                                          int row0, int k0, int ld,
                                          uint32_t sdst, int tid) {
    #pragma unroll
    for (int i = 0; i < 4; i++) {
        int gr = i * 128 + tid;          // 0..511
        int r  = gr >> 2;
        int sec = gr & 3;
        cp16(sdst + sw64((uint32_t)(r * 64 + sec * 16)),
             (const void*)(g + (long long)(row0 + r) * ld + (k0 + sec * 8)));
    }
}

// NN: load one 32(k) x 128(n) fp16 tile (256B rows), SW256-swizzled
__device__ __forceinline__ void load_tile_nn(const __half* __restrict__ g,
                                             int k0, int col0, int ld,
                                             uint32_t sdst, int tid) {
    #pragma unroll
    for (int i = 0; i < 4; i++) {
        int gr = i * 128 + tid;          // 0..511
        int r  = gr >> 4;
        int sec = gr & 15;
        cp16(sdst + sw256((uint32_t)(r * 256 + sec * 16)),
             (const void*)(g + (long long)(k0 + r) * ld + (col0 + sec * 8)));
    }
}

template<int EPI, bool BIAS, bool CAUSAL, bool KLIM, int TERMS, bool SKIPZ0, bool BNN>
__global__ void __launch_bounds__(128, 2)
gemm_mma(const __half* __restrict__ Ahi, const __half* __restrict__ Alo,
         const __half* __restrict__ Bhi, const __half* __restrict__ Blo,
         const float* __restrict__ bias,
         float* __restrict__ Cf, __half* __restrict__ Chi, __half* __restrict__ Clo,
         int K, int ldC,
         long long aB, long long bB, long long cB)
{
    const int bx = blockIdx.x, z = blockIdx.z;
    int by = blockIdx.y;
    if (CAUSAL && bx > by) return;
    if (KLIM) by = gridDim.y - 1 - by;    // longest tiles first

    extern __shared__ char smem[];
    const uint32_t stage0 = (smem_u32(smem) + 1023u) & ~1023u;

    const int tid  = threadIdx.x;
    const int lane = tid & 31;
    const int wid  = tid >> 5;            // 0..3
    const int wm   = (wid & 1) * 64;      // warp m offset
    const int wn   = (wid >> 1) * 64;     // warp n offset

    const __half* A_hi = Ahi + (long long)z * aB;
    const __half* A_lo = Alo + (long long)z * aB;
    const __half* B_hi = Bhi + (long long)z * bB;
    const __half* B_lo = Blo + (long long)z * bB;

    int nk = K >> 5;
    if (KLIM) { int lim = 4 * (by + 1); if (lim < nk) nk = lim; }
    const int row0 = by * 128;
    const int col0 = bx * 128;

    float acc[4][8][4];
    #pragma unroll
    for (int i = 0; i < 4; i++)
        #pragma unroll
        for (int j = 0; j < 8; j++)
            #pragma unroll
            for (int c = 0; c < 4; c++) acc[i][j][c] = 0.0f;

    // per-lane ldmatrix address components
    const int a_r = ((lane >> 3) & 1) * 8 + (lane & 7);   // + mi*16 + wm
    const int a_c = (lane >> 4) * 16;                      // + ks*32
    const int b_r = ((lane >> 4) & 1) * 8 + (lane & 7);    // + pair*16 + wn
    const int b_c = ((lane >> 3) & 1) * 16;                // + ks*32
    const int bt_r = ((lane >> 3) & 1) * 8 + (lane & 7);   // NN: k row in 16-block
    const int bt_c = ((lane >> 4) & 1) * 16;               // NN: n byte in 32B pair

    // prologue
    #pragma unroll
    for (int c = 0; c < NSTG - 1; c++) {
        uint32_t st = stage0 + c * STAGE_BYTES;
        load_tile(A_hi, row0, c * 32, K, st + 0 * TILE_BYTES, tid);
        load_tile(A_lo, row0, c * 32, K, st + 1 * TILE_BYTES, tid);
        if (BNN)
            load_tile_nn(B_hi, c * 32, col0, ldC, st + 2 * TILE_BYTES, tid);
        else
            load_tile(B_hi, col0, c * 32, K, st + 2 * TILE_BYTES, tid);
        if (!BNN && TERMS >= 3)
            load_tile(B_lo, col0, c * 32, K, st + 3 * TILE_BYTES, tid);
        cp_commit();
    }

    for (int k = 0; k < nk; k++) {
        const int s = k % NSTG;
        if (k < nk - 1) cp_wait_c<NSTG - 2>(); else cp_wait_c<0>();
        __syncthreads();

        const uint32_t sAh = stage0 + s * STAGE_BYTES + 0 * TILE_BYTES;
        const uint32_t sAl = sAh + TILE_BYTES;
        const uint32_t sBh = sAh + 2 * TILE_BYTES;
        const uint32_t sBl = sAh + 3 * TILE_BYTES;

        #pragma unroll
        for (int ks = 0; ks < 2; ks++) {
            uint32_t ah[4][4], bh[4][4];
            #pragma unroll
            for (int mi = 0; mi < 4; mi++)
                ldsm4(ah[mi], sAh + sw64((uint32_t)((wm + mi * 16 + a_r) * 64 + ks * 32 + a_c)));
            #pragma unroll
            for (int p = 0; p < 4; p++) {
                if (BNN)
                    ldsm4t(bh[p], sBh + sw256((uint32_t)((ks * 16 + bt_r) * 256 + wn * 2 + p * 32 + bt_c)));
                else
                    ldsm4(bh[p], sBh + sw64((uint32_t)((wn + p * 16 + b_r) * 64 + ks * 32 + b_c)));
            }
            // term 1: Ah*Bh
            #pragma unroll
            for (int mi = 0; mi < 4; mi++)
                #pragma unroll
                for (int nj = 0; nj < 8; nj++)
                    mma_f16(acc[mi][nj], ah[mi], &bh[nj >> 1][(nj & 1) * 2]);
            // term 2: Al*Bh
            {
                uint32_t al[4][4];
                #pragma unroll
                for (int mi = 0; mi < 4; mi++)
                    ldsm4(al[mi], sAl + sw64((uint32_t)((wm + mi * 16 + a_r) * 64 + ks * 32 + a_c)));
                #pragma unroll
                for (int mi = 0; mi < 4; mi++)
                    #pragma unroll
                    for (int nj = 0; nj < 8; nj++)
                        mma_f16(acc[mi][nj], al[mi], &bh[nj >> 1][(nj & 1) * 2]);
            }
            // term 3: Ah*Bl (NT only)
            if (!BNN && TERMS >= 3) {
                uint32_t bl[4][4];
                #pragma unroll
                for (int p = 0; p < 4; p++)
                    ldsm4(bl[p], sBl + sw64((uint32_t)((wn + p * 16 + b_r) * 64 + ks * 32 + b_c)));
                #pragma unroll
                for (int mi = 0; mi < 4; mi++)
                    #pragma unroll
                    for (int nj = 0; nj < 8; nj++)
                        mma_f16(acc[mi][nj], ah[mi], &bl[nj >> 1][(nj & 1) * 2]);
            }
        }

        // prefetch chunk k+NSTG-1 (tail placement — measured best)
        const int cl = k + NSTG - 1;
        if (cl < nk) {
            uint32_t st = stage0 + (cl % NSTG) * STAGE_BYTES;
            load_tile(A_hi, row0, cl * 32, K, st + 0 * TILE_BYTES, tid);
            load_tile(A_lo, row0, cl * 32, K, st + 1 * TILE_BYTES, tid);
            if (BNN)
                load_tile_nn(B_hi, cl * 32, col0, ldC, st + 2 * TILE_BYTES, tid);
            else
                load_tile(B_hi, col0, cl * 32, K, st + 2 * TILE_BYTES, tid);
            if (!BNN && TERMS >= 3)
                load_tile(B_lo, col0, cl * 32, K, st + 3 * TILE_BYTES, tid);
            cp_commit();
        }
    }

    // ---- epilogue (64x64 per warp) ----
    const float* bp = bias + (long long)z * DIM;
    const bool doF32 = (EPI == 0 || EPI >= 2) && !(SKIPZ0 && z == 0);
    #pragma unroll
    for (int mi = 0; mi < 4; mi++) {
        const int r0 = row0 + wm + mi * 16 + (lane >> 2);
        #pragma unroll
        for (int nj = 0; nj < 8; nj++) {
            const int c = col0 + wn + nj * 8 + (lane & 3) * 2;
            float v0 = acc[mi][nj][0], v1 = acc[mi][nj][1];
            float v2 = acc[mi][nj][2], v3 = acc[mi][nj][3];
            if (BIAS) {
                float b0 = bp[c], b1 = bp[c + 1];
                v0 += b0; v1 += b1; v2 += b0; v3 += b1;
            }
            if (doF32) {
                float* cp = Cf + (long long)z * cB + (long long)r0 * ldC + c;
                *(float2*)cp = make_float2(v0, v1);
                *(float2*)(cp + 8LL * ldC) = make_float2(v2, v3);
            }
            if (EPI == 1 || EPI == 2) {
                __half h0, l0, h1, l1;
                split1(v0, h0, l0); split1(v1, h1, l1);
                __half* hp = Chi + (long long)z * cB + (long long)r0 * ldC + c;
                __half* lp = Clo + (long long)z * cB + (long long)r0 * ldC + c;
                *(__half2*)hp = __halves2half2(h0, h1);
                *(__half2*)lp = __halves2half2(l0, l1);
                split1(v2, h0, l0); split1(v3, h1, l1);
                *(__half2*)(hp + 8LL * ldC) = __halves2half2(h0, h1);
                *(__half2*)(lp + 8LL * ldC) = __halves2half2(l0, l1);
            } else if (EPI == 3) {
                __half* hp = Chi + (long long)z * cB + (long long)r0 * ldC + c;
                *(__half2*)hp = __halves2half2(__float2half(v0), __float2half(v1));
                *(__half2*)(hp + 8LL * ldC) = __halves2half2(__float2half(v2), __float2half(v3));
            }
        }
    }
}

// ---------------------------------------------------------------------------
// elementwise fp32 -> fp16 hi/lo split
// ---------------------------------------------------------------------------
__global__ void split_kernel(const float* __restrict__ in,
                             __half* __restrict__ hi,
                             __half* __restrict__ lo, int n4)
{
    int i = blockIdx.x * blockDim.x + threadIdx.x;
    if (i >= n4) return;
    float4 v = ((const float4*)in)[i];
    __half h0, l0, h1, l1, h2, l2, h3, l3;
    split1(v.x, h0, l0); split1(v.y, h1, l1);
    split1(v.z, h2, l2); split1(v.w, h3, l3);
    __half2 ha = __halves2half2(h0, h1), hb = __halves2half2(h2, h3);
    __half2 la = __halves2half2(l0, l1), lb = __halves2half2(l2, l3);
    ((uint2*)hi)[i] = make_uint2(*(uint32_t*)&ha, *(uint32_t*)&hb);
    ((uint2*)lo)[i] = make_uint2(*(uint32_t*)&la, *(uint32_t*)&lb);
}

// transpose + split: fp32 [Z][R][C] -> fp16 hi/lo [Z][C][R]  (weights only)
__global__ void tsplit_kernel(const float* __restrict__ in,
                              __half* __restrict__ hi,
                              __half* __restrict__ lo, int R, int C)
{
    __shared__ float t[32][33];
    const long long zoff = (long long)blockIdx.z * R * C;
    const int c0 = blockIdx.x * 32, r0 = blockIdx.y * 32;
    const int tx = threadIdx.x, ty = threadIdx.y;
    #pragma unroll
    for (int i = 0; i < 4; i++)
        t[ty + 8 * i][tx] = in[zoff + (long long)(r0 + ty + 8 * i) * C + c0 + tx];
    __syncthreads();
    #pragma unroll
    for (int i = 0; i < 4; i++) {
        float v = t[tx][ty + 8 * i];
        __half h, l; split1(v, h, l);
        long long o = zoff + (long long)(c0 + ty + 8 * i) * R + r0 + tx;
        hi[o] = h; lo[o] = l;
    }
}

// ---------------------------------------------------------------------------
// combined biases: out[j*DIM + h] = sum_e b[e] * W_j[e, h],  j in {q,k,v}
// ---------------------------------------------------------------------------
__global__ void bias_combine_kernel(const float* __restrict__ b,
                                    const float* __restrict__ Wq,
                                    const float* __restrict__ Wk,
                                    const float* __restrict__ Wv,
                                    float* __restrict__ out)
{
    const int h = blockIdx.x * 256 + threadIdx.x;
    const float* W = (blockIdx.y == 0) ? Wq : (blockIdx.y == 1) ? Wk : Wv;
    float s = 0.0f;
    #pragma unroll 8
    for (int e = 0; e < DIM; e++) s += b[e] * W[(long long)e * DIM + h];
    out[blockIdx.y * DIM + h] = s;
}

// ---------------------------------------------------------------------------
// causal softmax fp32 scores -> fp16 hi/lo probs (vectorized)
// ---------------------------------------------------------------------------
__global__ __launch_bounds__(256)
void softmax_causal_kernel(const float* __restrict__ S,
                           __half* __restrict__ Phi,
                           __half* __restrict__ Plo)
{
    const int q = blockIdx.x, b = blockIdx.y;
    const long long off = ((long long)b * SEQ + q) * SEQ;
    const float* row = S + off;
    const int n = q + 1;
    const int n4 = n >> 2;
    const int rem = n & 3;
    const int tid = threadIdx.x;
    __shared__ float sh[8];

    float4 rv[2];
    float tail = 0.0f;
    int cnt = 0;
    float m = -INFINITY;
    for (int i = tid; i < n4; i += 256) {
        float4 v = ((const float4*)row)[i];
        rv[cnt++] = v;
        m = fmaxf(fmaxf(m, fmaxf(v.x, v.y)), fmaxf(v.z, v.w));
    }
    const bool hasTail = (tid < rem);
    if (hasTail) {
        tail = row[n4 * 4 + tid];
        m = fmaxf(m, tail);
    }
    #pragma unroll
    for (int o = 16; o; o >>= 1) m = fmaxf(m, __shfl_xor_sync(0xffffffffu, m, o));
    if ((tid & 31) == 0) sh[tid >> 5] = m;
    __syncthreads();
    float mr = sh[0];
    #pragma unroll
    for (int i = 1; i < 8; i++) mr = fmaxf(mr, sh[i]);
    __syncthreads();

    float s = 0.0f;
    #pragma unroll
    for (int j = 0; j < 2; j++)
        if (j < cnt) {
            rv[j].x = __expf(rv[j].x - mr); rv[j].y = __expf(rv[j].y - mr);
            rv[j].z = __expf(rv[j].z - mr); rv[j].w = __expf(rv[j].w - mr);
            s += rv[j].x + rv[j].y + rv[j].z + rv[j].w;
        }
    if (hasTail) { tail = __expf(tail - mr); s += tail; }
    #pragma unroll
    for (int o = 16; o; o >>= 1) s += __shfl_xor_sync(0xffffffffu, s, o);
    if ((tid & 31) == 0) sh[tid >> 5] = s;
    __syncthreads();
    float sr = 0.0f;
    #pragma unroll
    for (int i = 0; i < 8; i++) sr += sh[i];
    const float inv = 1.0f / sr;

    cnt = 0;
    for (int i = tid; i < n4; i += 256) {
        float4 v = rv[cnt++];
        float p0 = v.x * inv, p1 = v.y * inv, p2 = v.z * inv, p3 = v.w * inv;
        __half h0, l0, h1, l1, h2, l2, h3, l3;
        split1(p0, h0, l0); split1(p1, h1, l1);
        split1(p2, h2, l2); split1(p3, h3, l3);
        __half2 ha = __halves2half2(h0, h1), hb = __halves2half2(h2, h3);
        __half2 la = __halves2half2(l0, l1), lb = __halves2half2(l2, l3);
        ((uint2*)(Phi + off))[i] = make_uint2(*(uint32_t*)&ha, *(uint32_t*)&hb);
        ((uint2*)(Plo + off))[i] = make_uint2(*(uint32_t*)&la, *(uint32_t*)&lb);
    }
    if (hasTail) {
        float p = tail * inv;
        __half h, l; split1(p, h, l);
        Phi[off + n4 * 4 + tid] = h; Plo[off + n4 * 4 + tid] = l;
    }
    const int fend = ((q >> 7) + 1) << 7;
    const __half z16 = __float2half(0.0f);
    for (int i = n + tid; i < fend; i += 256) {
        Phi[off + i] = z16; Plo[off + i] = z16;
    }
}

// ---------------------------------------------------------------------------
extern "C" void kernel_launch(void* const* d_in, const int* in_sizes, int n_in,
                              void* d_out, int out_size)
{
    const float* x_batch = (const float*)d_in[0];
    const float* lin_w   = (const float*)d_in[1];
    const float* lin_b   = (const float*)d_in[2];
    const float* W_q     = (const float*)d_in[3];
    const float* W_k     = (const float*)d_in[4];
    const float* W_v     = (const float*)d_in[5];

    float* outF = (float*)d_out;
    float* outK = outF + (long long)BS * DIM;
    float* outV = outK + (long long)BS * DIM;

    __half *xb_hi, *xb_lo, *wT_hi, *wT_lo, *lwT_hi, *lwT_lo, *c_hi, *c_lo;
    __half *qkv_hi, *qkv_lo, *v_hi, *p_hi, *p_lo;
    float *bias3, *ss;
    cudaGetSymbolAddress((void**)&xb_hi, g_xb_hi); cudaGetSymbolAddress((void**)&xb_lo, g_xb_lo);
    cudaGetSymbolAddress((void**)&wT_hi, g_wT_hi); cudaGetSymbolAddress((void**)&wT_lo, g_wT_lo);
    cudaGetSymbolAddress((void**)&lwT_hi, g_lwT_hi); cudaGetSymbolAddress((void**)&lwT_lo, g_lwT_lo);
    cudaGetSymbolAddress((void**)&c_hi, g_c_hi);   cudaGetSymbolAddress((void**)&c_lo, g_c_lo);
    cudaGetSymbolAddress((void**)&bias3, g_bias);
    cudaGetSymbolAddress((void**)&qkv_hi, g_qkv_hi); cudaGetSymbolAddress((void**)&qkv_lo, g_qkv_lo);
    cudaGetSymbolAddress((void**)&v_hi, g_v_hi);
    cudaGetSymbolAddress((void**)&p_hi,  g_p_hi);  cudaGetSymbolAddress((void**)&p_lo,  g_p_lo);
    cudaGetSymbolAddress((void**)&ss, g_s);

    cudaFuncSetAttribute(gemm_mma<1, false, false, false, 3, false, false>, cudaFuncAttributeMaxDynamicSharedMemorySize, SMEM_DYN);
    cudaFuncSetAttribute(gemm_mma<2, true,  false, false, 3, true,  false>, cudaFuncAttributeMaxDynamicSharedMemorySize, SMEM_DYN);
    cudaFuncSetAttribute(gemm_mma<3, true,  false, false, 3, false, false>, cudaFuncAttributeMaxDynamicSharedMemorySize, SMEM_DYN);
    cudaFuncSetAttribute(gemm_mma<0, false, true,  false, 3, false, false>, cudaFuncAttributeMaxDynamicSharedMemorySize, SMEM_DYN);
    cudaFuncSetAttribute(gemm_mma<0, false, false, true,  2, false, true >, cudaFuncAttributeMaxDynamicSharedMemorySize, SMEM_DYN);

    const long long DD   = (long long)DIM * DIM;
    const long long HOFF = (long long)HROWS * DIM;
    const long long SOFF = (long long)HB * SEQ * SEQ;
    const long long VOFF = (long long)HB * SEQ * DIM;

    static cudaStream_t s2 = nullptr;
    static cudaEvent_t e0 = nullptr, e2 = nullptr, e3 = nullptr, eV = nullptr, eE = nullptr;
    static bool tried = false;
    if (!tried) {
        tried = true;
        if (cudaStreamCreateWithFlags(&s2, cudaStreamNonBlocking) != cudaSuccess) s2 = nullptr;
        if (s2) {
            cudaEventCreateWithFlags(&e0, cudaEventDisableTiming);
            cudaEventCreateWithFlags(&e2, cudaEventDisableTiming);
            cudaEventCreateWithFlags(&e3, cudaEventDisableTiming);
            cudaEventCreateWithFlags(&eV, cudaEventDisableTiming);
            cudaEventCreateWithFlags(&eE, cudaEventDisableTiming);
        }
    }
    const bool ok = (s2 != nullptr);
    cudaStream_t sb = ok ? s2 : (cudaStream_t)0;

    // ================= fork: prep on side, xb split on main =================
    if (ok) { cudaEventRecord(e0, 0); cudaStreamWaitEvent(sb, e0, 0); }
    {
        dim3 g(DIM / 32, DIM / 32, 1), t(32, 8);
        tsplit_kernel<<<g, t, 0, sb>>>(lin_w, lwT_hi, lwT_lo, DIM, DIM);
        tsplit_kernel<<<g, t, 0, sb>>>(W_q, wT_hi + 0 * DD, wT_lo + 0 * DD, DIM, DIM);
        tsplit_kernel<<<g, t, 0, sb>>>(W_k, wT_hi + 1 * DD, wT_lo + 1 * DD, DIM, DIM);
        tsplit_kernel<<<g, t, 0, sb>>>(W_v, wT_hi + 2 * DD, wT_lo + 2 * DD, DIM, DIM);
    }
    bias_combine_kernel<<<dim3(DIM / 256, 3), 256, 0, sb>>>(lin_b, W_q, W_k, W_v, bias3);
    {
        dim3 g(DIM / 128, DIM / 128, 3);
        gemm_mma<1, false, false, false, 3, false, false><<<g, 128, SMEM_DYN, sb>>>(
            wT_hi, wT_lo, lwT_hi, lwT_lo, nullptr,
            nullptr, c_hi, c_lo, DIM, DIM, DD, 0, DD);
    }
    if (ok) cudaEventRecord(e2, sb);

    split_kernel<<<(BS * DIM / 4 + 255) / 256, 256>>>(x_batch, xb_hi, xb_lo, BS * DIM / 4);
    if (ok) { cudaStreamWaitEvent(0, e2, 0); cudaEventRecord(e3, 0); cudaStreamWaitEvent(sb, e3, 0); }

    // ====== side pipeline (half 1, b4..7): QKV -> scores -> softmax =========
    {
        dim3 g(DIM / 128, HROWS / 128, 2);
        gemm_mma<2, true, false, false, 3, true, false><<<g, 128, SMEM_DYN, sb>>>(
            xb_hi + HOFF, xb_lo + HOFF, c_hi, c_lo, bias3,
            outF + HOFF, qkv_hi + HOFF, qkv_lo + HOFF, DIM, DIM,
            0, DD, (long long)BS * DIM);
    }
    {
        dim3 g(SEQ / 128, SEQ / 128, HB);
        gemm_mma<0, false, true, false, 3, false, false><<<g, 128, SMEM_DYN, sb>>>(
            qkv_hi + HOFF, qkv_lo + HOFF,
            qkv_hi + (long long)BS * DIM + HOFF, qkv_lo + (long long)BS * DIM + HOFF,
            nullptr, ss + SOFF, nullptr, nullptr, DIM, SEQ,
            (long long)SEQ * DIM, (long long)SEQ * DIM, (long long)SEQ * SEQ);
    }
    {
        dim3 g(SEQ, HB);
        softmax_causal_kernel<<<g, 256, 0, sb>>>(ss + SOFF, p_hi + SOFF, p_lo + SOFF);
    }

    // ====== main: V GEMM (fp32 cache + hi-only split; EPI=3) ================
    {
        dim3 g(DIM / 128, BS / 128, 1);
        gemm_mma<3, true, false, false, 3, false, false><<<g, 128, SMEM_DYN>>>(
            xb_hi, xb_lo, c_hi + 2 * DD, c_lo + 2 * DD, bias3 + 2 * DIM,
            outV, v_hi, nullptr, DIM, DIM, 0, 0, (long long)BS * DIM);
    }
    if (ok) cudaEventRecord(eV, 0);

    // ====== side: PV half 1 =================================================
    if (ok) cudaStreamWaitEvent(sb, eV, 0);
    {
        dim3 g(DIM / 128, SEQ / 128, HB);
        gemm_mma<0, false, false, true, 2, false, true><<<g, 128, SMEM_DYN, sb>>>(
            p_hi + SOFF, p_lo + SOFF, v_hi + VOFF, nullptr, nullptr,
            outF + HOFF, nullptr, nullptr, SEQ, DIM,
            (long long)SEQ * SEQ, (long long)SEQ * DIM, (long long)SEQ * DIM);
    }
    if (ok) cudaEventRecord(eE, sb);

    // ====== main pipeline (half 0, b0..3) ====================================
    {
        dim3 g(DIM / 128, HROWS / 128, 2);
        gemm_mma<2, true, false, false, 3, true, false><<<g, 128, SMEM_DYN>>>(
            xb_hi, xb_lo, c_hi, c_lo, bias3,
            outF, qkv_hi, qkv_lo, DIM, DIM,
            0, DD, (long long)BS * DIM);
    }
    {
        dim3 g(SEQ / 128, SEQ / 128, HB);
        gemm_mma<0, false, true, false, 3, false, false><<<g, 128, SMEM_DYN>>>(
            qkv_hi, qkv_lo,
            qkv_hi + (long long)BS * DIM, qkv_lo + (long long)BS * DIM,
            nullptr, ss, nullptr, nullptr, DIM, SEQ,
            (long long)SEQ * DIM, (long long)SEQ * DIM, (long long)SEQ * SEQ);
    }
    {
        dim3 g(SEQ, HB);
        softmax_causal_kernel<<<g, 256>>>(ss, p_hi, p_lo);
    }
    {
        dim3 g(DIM / 128, SEQ / 128, HB);
        gemm_mma<0, false, false, true, 2, false, true><<<g, 128, SMEM_DYN>>>(
            p_hi, p_lo, v_hi, nullptr, nullptr,
            outF, nullptr, nullptr, SEQ, DIM,
            (long long)SEQ * SEQ, (long long)SEQ * DIM, (long long)SEQ * DIM);
    }
    if (ok) cudaStreamWaitEvent(0, eE, 0);
}